// round 15
// baseline (speedup 1.0000x reference)
#include <cuda_runtime.h>
#include <math.h>
#include <stdint.h>

#define S_ 64
#define C_ 256
#define NN_ 4096
#define B_ 16
#define M_ 128
#define P_ 2080
#define TINV 10.0f
#define NEGIOU 0.5f
#define TP 64
#define PTILES 33           // 33*64 = 2112 >= 2080
#define CK 16
#define CHUNKS (C_/CK)      // 16
#define QB (PTILES*B_)      // 528 query blocks
#define GRID (QB + M_)      // + 128 video blocks
#define NST 3               // cp.async pipeline depth
#define VROW 128            // dup-v row (floats): slots [4g,4g+4) and [64+4g,64+4g+4)
#define VSTG (CK*VROW)      // floats per v stage (2048)

// scratch (device globals; no allocation allowed)
__device__ int   g_midx[P_];
__device__ int   g_b2s[B_];
__device__ int   g_m2s[M_];
__device__ int   g_s2b[S_];
__device__ float g_sfn[S_*C_];   // [s][c] row-major (video role)
__device__ float g_sft[C_*S_];   // [c][s] transposed (query role)
__device__ float g_pl[M_];
__device__ float g_lossv[M_];
__device__ float g_qpart[QB*S_];

// ---------------------------------------------------------------------------
// helpers
// ---------------------------------------------------------------------------
__device__ __forceinline__ void cpa4(void* dst, const void* src) {
    uint32_t d = (uint32_t)__cvta_generic_to_shared(dst);
    asm volatile("cp.async.ca.shared.global [%0], [%1], 4;" :: "r"(d), "l"(src));
}
__device__ __forceinline__ void cpa16(void* dst, const void* src) {
    uint32_t d = (uint32_t)__cvta_generic_to_shared(dst);
    asm volatile("cp.async.cg.shared.global [%0], [%1], 16;" :: "r"(d), "l"(src));
}
__device__ __forceinline__ void cpa_commit() { asm volatile("cp.async.commit_group;"); }
__device__ __forceinline__ void cpa_wait(int n) {
    if (n >= 2)      asm volatile("cp.async.wait_group 2;");
    else if (n == 1) asm volatile("cp.async.wait_group 1;");
    else             asm volatile("cp.async.wait_group 0;");
}

__device__ __forceinline__ uint64_t fma2(uint64_t a, uint64_t b, uint64_t c) {
    uint64_t d; asm("fma.rn.f32x2 %0, %1, %2, %3;" : "=l"(d) : "l"(a), "l"(b), "l"(c));
    return d;
}
__device__ __forceinline__ void unpack2(uint64_t v, float& lo, float& hi) {
    asm("mov.b64 {%0, %1}, %2;" : "=f"(lo), "=f"(hi) : "l"(v));
}

// ---------------------------------------------------------------------------
// Kernel 1: sf normalize (64 blocks x 256) + transposed copy + setup (blk 0)
// mask2d is static config: triu(64x64), P=2080, generated analytically.
// ---------------------------------------------------------------------------
__global__ void sfnorm_setup_kernel(const float* __restrict__ sf,
                                    const int* __restrict__ nsent,
                                    const int* __restrict__ ntarg) {
    int s = blockIdx.x;
    int t = threadIdx.x; // == c

    __shared__ int sh_cs[B_ + 1];
    __shared__ int sh_ct[S_];
    __shared__ int sh_nt[S_];
    __shared__ int sh_ns[B_];
    __shared__ int sh_wtot;
    __shared__ float red[8];

    if (s == 0) {
        int lane = t & 31;
        int warp = t >> 5;
        if (warp == 0) {
            int v = (lane < B_) ? nsent[lane] : 0;
            if (lane < B_) sh_ns[lane] = v;
            int incl = v;
#pragma unroll
            for (int o = 1; o < 32; o <<= 1) {
                int up = __shfl_up_sync(0xffffffffu, incl, o);
                if (lane >= o) incl += up;
            }
            if (lane < B_) sh_cs[lane] = incl - v;
            if (lane == B_ - 1) sh_cs[B_] = incl;
        }
        if (warp == 1 || warp == 2) {
            int idx = (warp - 1) * 32 + lane;
            int v = ntarg[idx];
            sh_nt[idx] = v;
            int incl = v;
#pragma unroll
            for (int o = 1; o < 32; o <<= 1) {
                int up = __shfl_up_sync(0xffffffffu, incl, o);
                if (lane >= o) incl += up;
            }
            if (warp == 1) {
                sh_ct[idx] = incl - v;
                if (lane == 31) sh_wtot = incl;
            }
        }
        __syncthreads();
        if (warp == 2) {
            int idx = 32 + lane;
            int v = sh_nt[idx];
            int incl = v;
#pragma unroll
            for (int o = 1; o < 32; o <<= 1) {
                int up = __shfl_up_sync(0xffffffffu, incl, o);
                if (lane >= o) incl += up;
            }
            sh_ct[idx] = incl - v + sh_wtot;
        }
        if (t < 64) {
            int off = t * 64 - (t * (t - 1)) / 2;
            for (int c = t; c < 64; c++)
                g_midx[off + (c - t)] = t * 64 + c;
        }
        __syncthreads();
        if (t < B_) {
            int st = sh_cs[t];
            g_b2s[t] = st;
            for (int j = 0; j < sh_ns[t]; j++)
                if (st + j < S_) g_s2b[st + j] = t;
        }
        if (t < S_) {
            int st = sh_ct[t];
            for (int j = 0; j < sh_nt[t]; j++)
                if (st + j < M_) g_m2s[st + j] = t;
        }
    }

    float v = sf[s * C_ + t];
    float x = v * v;
#pragma unroll
    for (int o = 16; o; o >>= 1) x += __shfl_down_sync(0xffffffffu, x, o);
    if ((t & 31) == 0) red[t >> 5] = x;
    __syncthreads();
    if (t == 0) {
        float acc = 0.f;
#pragma unroll
        for (int i = 0; i < 8; i++) acc += red[i];
        red[0] = acc;
    }
    __syncthreads();
    float n = fmaxf(sqrtf(red[0]), 1e-12f);
    float nv = v / n;
    g_sfn[s * C_ + t] = nv;
    g_sft[t * S_ + s] = nv;
}

// ---------------------------------------------------------------------------
// Kernel 2 (mega): blocks [0,QB): inter-query; blocks [QB,QB+M): inter-video
// Query: CK=16, NST=3 pipeline; v stored DUPLICATED in smem so each LDS.128
// yields two ready f32x2 dup pairs (no packdup MOVs in the hot loop).
// Layout per row (128 floats): group g owns [4g,4g+4) (j=0,1) and
// [64+4g,64+4g+4) (j=2,3) — disjoint, contiguous per-warp 256B reads.
// ---------------------------------------------------------------------------
__global__ __launch_bounds__(128, 4) void mega_kernel(const float* __restrict__ video,
                                                      const float* __restrict__ iou2d,
                                                      const float* __restrict__ iou2ds) {
    __shared__ __align__(16) float smem_raw[NST*VSTG + NST*CK*S_ + 1024];
    int bid = blockIdx.x;
    int tid = threadIdx.x;

    if (bid < QB) {
        // ================= QUERY ROLE =================
        float* vt   = smem_raw;                         // [NST][CK][VROW] 24KB
        float* sfc  = smem_raw + NST*VSTG;              // [NST][CK*64]   12KB
        float* part = smem_raw + NST*VSTG + NST*CK*S_;  // [64][16]        4KB

        int b  = bid / PTILES;
        int pt = bid - b * PTILES;
        int sb = g_b2s[b];
        int pi = tid & 15;     // p-group: p = ptbase + pi*4 + j
        int si = tid >> 4;     // s-group: s = si*8 + 2a + h

        int ptbase = pt * TP;
        int pcol_l = tid & 63; // loader's p column
        int ih = tid >> 6;     // loader's c-half
        int pc = ptbase + pcol_l;
        int fidx = g_midx[pc < P_ ? pc : (P_ - 1)];
        const float* vbase = video + (size_t)sb * C_ * NN_;

        // loader's dup destination (2 consecutive floats)
        int lg = pcol_l >> 2, lj = pcol_l & 3;
        int lcol = (lj < 2) ? (lg * 4 + lj * 2) : (64 + lg * 4 + (lj - 2) * 2);

        uint64_t acc2[4][4];   // [a(s-pair)][j(p)]
        uint64_t accn2[4];
#pragma unroll
        for (int a = 0; a < 4; a++)
#pragma unroll
            for (int j = 0; j < 4; j++) acc2[a][j] = 0ull;
#pragma unroll
        for (int j = 0; j < 4; j++) accn2[j] = 0ull;

        auto load_stage = [&](int chunk, int st) {
            int cb = chunk * CK;
            float* vdst = vt + st * VSTG;
            float* sdst = sfc + st * CK * S_;
#pragma unroll
            for (int i2 = 0; i2 < 8; i2++) {
                int i = ih * 8 + i2;
                const float* src = vbase + (size_t)(cb + i) * NN_ + fidx;
                cpa4(&vdst[i * VROW + lcol], src);
                cpa4(&vdst[i * VROW + lcol + 1], src);
            }
            const float* ssrc = g_sft + cb * S_;
#pragma unroll
            for (int k = 0; k < 2; k++) {
                int u = tid + k * 128;       // 16B unit index (256 units)
                cpa16(&sdst[u * 4], &ssrc[u * 4]);
            }
            cpa_commit();
        };

        load_stage(0, 0);
        load_stage(1, 1);
        load_stage(2, 2);

        int st = 0;
        for (int k = 0; k < CHUNKS; k++) {
            cpa_wait(CHUNKS - 1 - k);
            __syncthreads();
            const float* vrow = vt + st * VSTG;
            const float* srow = sfc + st * CK * S_;
#pragma unroll
            for (int i = 0; i < CK; i++) {
                ulonglong2 v01 = *(const ulonglong2*)&vrow[i * VROW + pi * 4];       // {v0,v0},{v1,v1}
                ulonglong2 v23 = *(const ulonglong2*)&vrow[i * VROW + 64 + pi * 4];  // {v2,v2},{v3,v3}
                const ulonglong2* sp = (const ulonglong2*)&srow[i * S_ + si * 8];
                ulonglong2 s01 = sp[0];
                ulonglong2 s23 = sp[1];
                uint64_t vp[4] = { v01.x, v01.y, v23.x, v23.y };
                accn2[0] = fma2(vp[0], vp[0], accn2[0]);
                accn2[1] = fma2(vp[1], vp[1], accn2[1]);
                accn2[2] = fma2(vp[2], vp[2], accn2[2]);
                accn2[3] = fma2(vp[3], vp[3], accn2[3]);
                uint64_t ss[4] = { s01.x, s01.y, s23.x, s23.y };
#pragma unroll
                for (int a = 0; a < 4; a++)
#pragma unroll
                    for (int j = 0; j < 4; j++)
                        acc2[a][j] = fma2(ss[a], vp[j], acc2[a][j]);
            }
            __syncthreads();
            if (k + NST < CHUNKS) load_stage(k + NST, st);
            st = (st == NST - 1) ? 0 : st + 1;
        }

        // epilogue
        float inv[4];
#pragma unroll
        for (int j = 0; j < 4; j++) {
            float nlo, nhi;
            unpack2(accn2[j], nlo, nhi);
            inv[j] = TINV / fmaxf(sqrtf(nlo), 1e-12f);
        }

#pragma unroll
        for (int a = 0; a < 4; a++) {
            float dlo[4], dhi[4];
#pragma unroll
            for (int j = 0; j < 4; j++) unpack2(acc2[a][j], dlo[j], dhi[j]);
#pragma unroll
            for (int h = 0; h < 2; h++) {
                int s = si * 8 + 2 * a + h;
                const float* dv = h ? dhi : dlo;
                bool samevid = (g_s2b[s] == b);
                float sum = 0.f;
#pragma unroll
                for (int j = 0; j < 4; j++) {
                    int p = ptbase + pi * 4 + j;
                    if (p < P_) {
                        bool excl = false;
                        if (samevid) {
                            float io = iou2d[s * NN_ + g_midx[p]];
                            excl = (io > NEGIOU);
                        }
                        if (!excl) sum += __expf(dv[j] * inv[j]);
                    }
                }
                part[s * 16 + pi] = sum;
            }
        }
        __syncthreads();
        if (tid < S_) {
            float tot = 0.f;
#pragma unroll
            for (int kk = 0; kk < 16; kk++) tot += part[tid * 16 + kk];
            g_qpart[bid * S_ + tid] = tot;
        }
    } else {
        // ================= VIDEO ROLE =================
        int m = bid - QB;
        int sm = g_m2s[m];
        float* sv   = smem_raw;                          // [128]
        int*   sidx = (int*)(smem_raw + 128);            // [128]
        float* sv2  = smem_raw + 256;                    // [256] normalized v
        float* alls = smem_raw + 512;                    // [64]
        float* red  = smem_raw + 576;                    // [4]

        // argmax over P of iou2ds[m, midx[p]] (tie -> lowest p)
        float best = -1e30f;
        int bi = 0;
        for (int p = tid; p < P_; p += 128) {
            float v = iou2ds[m * NN_ + g_midx[p]];
            if (v > best) { best = v; bi = p; }
        }
        sv[tid] = best; sidx[tid] = bi;
        __syncthreads();
        for (int o = 64; o; o >>= 1) {
            if (tid < o) {
                float vo = sv[tid + o]; int io = sidx[tid + o];
                if (vo > sv[tid] || (vo == sv[tid] && io < sidx[tid])) {
                    sv[tid] = vo; sidx[tid] = io;
                }
            }
            __syncthreads();
        }
        int pflat = g_midx[sidx[0]];
        __syncthreads();

        // load 2 channels per thread, compute norm
        float vc0 = video[((size_t)sm * C_ + tid) * NN_ + pflat];
        float vc1 = video[((size_t)sm * C_ + tid + 128) * NN_ + pflat];
        float x = vc0 * vc0 + vc1 * vc1;
#pragma unroll
        for (int o = 16; o; o >>= 1) x += __shfl_down_sync(0xffffffffu, x, o);
        if ((tid & 31) == 0) red[tid >> 5] = x;
        __syncthreads();
        float nrm = fmaxf(sqrtf(red[0] + red[1] + red[2] + red[3]), 1e-12f);
        sv2[tid] = vc0 / nrm;
        sv2[tid + 128] = vc1 / nrm;
        __syncthreads();

        // dots against all 64 normalized sentence vectors
        int w = tid >> 5, l = tid & 31;
#pragma unroll
        for (int k = 0; k < 16; k++) {
            int s = w * 16 + k;
            float acc = 0.f;
#pragma unroll
            for (int c = l; c < C_; c += 32) acc += sv2[c] * g_sfn[s * C_ + c];
#pragma unroll
            for (int o = 16; o; o >>= 1) acc += __shfl_down_sync(0xffffffffu, acc, o);
            if (l == 0) alls[s] = acc;
        }
        __syncthreads();
        if (tid == 0) {
            float pl = alls[sm] * TINV;
            float neg = 0.f;
            for (int s = 0; s < S_; s++)
                if (s != sm) neg += expf(alls[s] * TINV);
            g_pl[m] = pl;
            g_lossv[m] = logf(expf(pl) + neg) - pl;
        }
    }
}

// ---------------------------------------------------------------------------
// Kernel 3: qpart reduce (coalesced) + per-moment losses -> mean (1 x 1024)
// ---------------------------------------------------------------------------
__global__ void final_kernel(float* __restrict__ out) {
    int t = threadIdx.x;
    __shared__ float qn[16][S_];
    __shared__ float qq[S_];
    __shared__ float red[32];
    {
        int s  = t & 63;
        int i0 = t >> 6;            // 0..15
        float acc = 0.f;
        for (int i = i0; i < QB; i += 16)   // 33 coalesced, independent loads
            acc += g_qpart[i * S_ + s];
        qn[i0][s] = acc;
    }
    __syncthreads();
    if (t < S_) {
        float x = 0.f;
#pragma unroll
        for (int k = 0; k < 16; k++) x += qn[k][t];
        qq[t] = x;
    }
    __syncthreads();

    float v = 0.f;
    if (t < M_) {
        int sm = g_m2s[t];
        float pl = g_pl[t];
        float lq = logf(expf(pl) + qq[sm]) - pl;
        v = g_lossv[t] + lq;
    }
#pragma unroll
    for (int o = 16; o; o >>= 1) v += __shfl_down_sync(0xffffffffu, v, o);
    if ((t & 31) == 0) red[t >> 5] = v;
    __syncthreads();
    if (t == 0) {
        float acc = 0.f;
#pragma unroll
        for (int i = 0; i < 4; i++) acc += red[i];
        out[0] = acc / (float)M_;
    }
}

// ---------------------------------------------------------------------------
extern "C" void kernel_launch(void* const* d_in, const int* in_sizes, int n_in,
                              void* d_out, int out_size) {
    const float* video = (const float*)d_in[0];         // (S,C,N,N)
    const float* sents = (const float*)d_in[1];         // (S,C)
    const float* iou2d = (const float*)d_in[2];         // (S,N,N)
    const float* iou2ds = (const float*)d_in[3];        // (M,N,N)
    const int* nsent = (const int*)d_in[4];             // (B,)
    const int* ntarg = (const int*)d_in[5];             // (S,)
    float* out = (float*)d_out;

    sfnorm_setup_kernel<<<S_, 256>>>(sents, nsent, ntarg);
    mega_kernel<<<GRID, 128>>>(video, iou2d, iou2ds);
    final_kernel<<<1, 1024>>>(out);
}

// round 16
// speedup vs baseline: 1.2982x; 1.2982x over previous
#include <cuda_runtime.h>
#include <math.h>
#include <stdint.h>

#define S_ 64
#define C_ 256
#define NN_ 4096
#define B_ 16
#define M_ 128
#define P_ 2080
#define TINV 10.0f
#define NEGIOU 0.5f
#define TP 64
#define PTILES 33           // 33*64 = 2112 >= 2080
#define CK 16
#define CHUNKS (C_/CK)      // 16
#define QB (PTILES*B_)      // 528 query blocks
#define GRID (QB + M_)      // + 128 video blocks
#define NST 3               // cp.async pipeline depth

// scratch (device globals; no allocation allowed)
__device__ int   g_midx[P_];
__device__ int   g_b2s[B_];
__device__ int   g_m2s[M_];
__device__ int   g_s2b[S_];
__device__ float g_sfn[S_*C_];   // [s][c] row-major (video role)
__device__ float g_sft[C_*S_];   // [c][s] transposed (query role)
__device__ float g_pl[M_];
__device__ float g_lossv[M_];
__device__ float g_qpart[QB*S_];

// ---------------------------------------------------------------------------
// helpers
// ---------------------------------------------------------------------------
__device__ __forceinline__ void cpa4(void* dst, const void* src) {
    uint32_t d = (uint32_t)__cvta_generic_to_shared(dst);
    asm volatile("cp.async.ca.shared.global [%0], [%1], 4;" :: "r"(d), "l"(src));
}
__device__ __forceinline__ void cpa16(void* dst, const void* src) {
    uint32_t d = (uint32_t)__cvta_generic_to_shared(dst);
    asm volatile("cp.async.cg.shared.global [%0], [%1], 16;" :: "r"(d), "l"(src));
}
__device__ __forceinline__ void cpa_commit() { asm volatile("cp.async.commit_group;"); }
__device__ __forceinline__ void cpa_wait1()  { asm volatile("cp.async.wait_group 1;"); }
__device__ __forceinline__ void cpa_wait0()  { asm volatile("cp.async.wait_group 0;"); }

__device__ __forceinline__ uint64_t packdup(float x) {
    uint64_t r; asm("mov.b64 %0, {%1, %1};" : "=l"(r) : "f"(x)); return r;
}
__device__ __forceinline__ uint64_t fma2(uint64_t a, uint64_t b, uint64_t c) {
    uint64_t d; asm("fma.rn.f32x2 %0, %1, %2, %3;" : "=l"(d) : "l"(a), "l"(b), "l"(c));
    return d;
}
__device__ __forceinline__ void unpack2(uint64_t v, float& lo, float& hi) {
    asm("mov.b64 {%0, %1}, %2;" : "=f"(lo), "=f"(hi) : "l"(v));
}

// ---------------------------------------------------------------------------
// Kernel 1: sf normalize (64 blocks x 256) + transposed copy + setup (blk 0)
// mask2d is static config: triu(64x64), P=2080, generated analytically.
// ---------------------------------------------------------------------------
__global__ void sfnorm_setup_kernel(const float* __restrict__ sf,
                                    const int* __restrict__ nsent,
                                    const int* __restrict__ ntarg) {
    int s = blockIdx.x;
    int t = threadIdx.x; // == c

    __shared__ int sh_cs[B_ + 1];
    __shared__ int sh_ct[S_];
    __shared__ int sh_nt[S_];
    __shared__ int sh_ns[B_];
    __shared__ int sh_wtot;
    __shared__ float red[8];

    if (s == 0) {
        int lane = t & 31;
        int warp = t >> 5;
        if (warp == 0) {
            int v = (lane < B_) ? nsent[lane] : 0;
            if (lane < B_) sh_ns[lane] = v;
            int incl = v;
#pragma unroll
            for (int o = 1; o < 32; o <<= 1) {
                int up = __shfl_up_sync(0xffffffffu, incl, o);
                if (lane >= o) incl += up;
            }
            if (lane < B_) sh_cs[lane] = incl - v;
            if (lane == B_ - 1) sh_cs[B_] = incl;
        }
        if (warp == 1 || warp == 2) {
            int idx = (warp - 1) * 32 + lane;
            int v = ntarg[idx];
            sh_nt[idx] = v;
            int incl = v;
#pragma unroll
            for (int o = 1; o < 32; o <<= 1) {
                int up = __shfl_up_sync(0xffffffffu, incl, o);
                if (lane >= o) incl += up;
            }
            if (warp == 1) {
                sh_ct[idx] = incl - v;
                if (lane == 31) sh_wtot = incl;
            }
        }
        __syncthreads();
        if (warp == 2) {
            int idx = 32 + lane;
            int v = sh_nt[idx];
            int incl = v;
#pragma unroll
            for (int o = 1; o < 32; o <<= 1) {
                int up = __shfl_up_sync(0xffffffffu, incl, o);
                if (lane >= o) incl += up;
            }
            sh_ct[idx] = incl - v + sh_wtot;
        }
        if (t < 64) {
            int off = t * 64 - (t * (t - 1)) / 2;
            for (int c = t; c < 64; c++)
                g_midx[off + (c - t)] = t * 64 + c;
        }
        __syncthreads();
        if (t < B_) {
            int st = sh_cs[t];
            g_b2s[t] = st;
            for (int j = 0; j < sh_ns[t]; j++)
                if (st + j < S_) g_s2b[st + j] = t;
        }
        if (t < S_) {
            int st = sh_ct[t];
            for (int j = 0; j < sh_nt[t]; j++)
                if (st + j < M_) g_m2s[st + j] = t;
        }
    }

    float v = sf[s * C_ + t];
    float x = v * v;
#pragma unroll
    for (int o = 16; o; o >>= 1) x += __shfl_down_sync(0xffffffffu, x, o);
    if ((t & 31) == 0) red[t >> 5] = x;
    __syncthreads();
    if (t == 0) {
        float acc = 0.f;
#pragma unroll
        for (int i = 0; i < 8; i++) acc += red[i];
        red[0] = acc;
    }
    __syncthreads();
    float n = fmaxf(sqrtf(red[0]), 1e-12f);
    float nv = v / n;
    g_sfn[s * C_ + t] = nv;
    g_sft[t * S_ + s] = nv;
}

// ---------------------------------------------------------------------------
// Kernel 2 (mega): blocks [0,QB): inter-query; blocks [QB,QB+M): inter-video
// Query: proven R7 datapath (CK=16, NST=3, packdup FMA2), but with ONE
// barrier per chunk: wait -> sync -> prefetch k+2 into stage (k+2)%3 ->
// compute stage k%3. The iter-k barrier guarantees stage (k+2)%3 (consumed
// at iter k-1) is free before the prefetch overwrites it.
// ---------------------------------------------------------------------------
__global__ __launch_bounds__(128, 4) void mega_kernel(const float* __restrict__ video,
                                                      const float* __restrict__ iou2d,
                                                      const float* __restrict__ iou2ds) {
    __shared__ __align__(16) char smem_raw[NST*8192 + 4096];
    int bid = blockIdx.x;
    int tid = threadIdx.x;

    if (bid < QB) {
        // ================= QUERY ROLE =================
        float* vt   = (float*)smem_raw;                      // [NST][CK][TP] 12KB
        float* sfc  = (float*)(smem_raw + NST*4096);         // [NST][CK*64]  12KB
        float* part = (float*)(smem_raw + NST*8192);         // [64][16]       4KB

        int b  = bid / PTILES;
        int pt = bid - b * PTILES;
        int sb = g_b2s[b];
        int pi = tid & 15;     // p-group: p = ptbase + pi*4 + j
        int si = tid >> 4;     // s-group: s = si*8 + 2a + h

        int ptbase = pt * TP;
        int pcol_l = tid & 63; // loader's p column
        int ih = tid >> 6;     // loader's c-half
        int pc = ptbase + pcol_l;
        int fidx = g_midx[pc < P_ ? pc : (P_ - 1)];
        const float* vbase = video + (size_t)sb * C_ * NN_;

        uint64_t acc2[4][4];   // [a(s-pair)][j(p)]
        uint64_t accn2[4];
#pragma unroll
        for (int a = 0; a < 4; a++)
#pragma unroll
            for (int j = 0; j < 4; j++) acc2[a][j] = 0ull;
#pragma unroll
        for (int j = 0; j < 4; j++) accn2[j] = 0ull;

        auto load_stage = [&](int chunk, int st) {
            int cb = chunk * CK;
            float* vdst = vt + st * CK * TP;
            float* sdst = sfc + st * CK * S_;
#pragma unroll
            for (int i2 = 0; i2 < 8; i2++) {
                int i = ih * 8 + i2;
                cpa4(&vdst[i * TP + pcol_l], vbase + (size_t)(cb + i) * NN_ + fidx);
            }
            const float* ssrc = g_sft + cb * S_;
#pragma unroll
            for (int k = 0; k < 2; k++) {
                int u = tid + k * 128;       // 16B unit index (256 units)
                cpa16(&sdst[u * 4], &ssrc[u * 4]);
            }
            cpa_commit();
        };

        load_stage(0, 0);
        load_stage(1, 1);

        for (int k = 0; k < CHUNKS; k++) {
            if (k < CHUNKS - 1) cpa_wait1(); else cpa_wait0();
            __syncthreads();   // chunk k visible; stage (k+2)%3 free
            if (k + 2 < CHUNKS) load_stage(k + 2, (k + 2) % NST);
            int st = k % NST;
            const float* vrow = vt + st * CK * TP;
            const float* srow = sfc + st * CK * S_;
#pragma unroll
            for (int i = 0; i < CK; i++) {
                float4 vld = *(const float4*)&vrow[i * TP + pi * 4];
                const ulonglong2* sp = (const ulonglong2*)&srow[i * S_ + si * 8];
                ulonglong2 s01 = sp[0];
                ulonglong2 s23 = sp[1];
                uint64_t vp[4];
                vp[0] = packdup(vld.x); vp[1] = packdup(vld.y);
                vp[2] = packdup(vld.z); vp[3] = packdup(vld.w);
                accn2[0] = fma2(vp[0], vp[0], accn2[0]);
                accn2[1] = fma2(vp[1], vp[1], accn2[1]);
                accn2[2] = fma2(vp[2], vp[2], accn2[2]);
                accn2[3] = fma2(vp[3], vp[3], accn2[3]);
                uint64_t ss[4] = { s01.x, s01.y, s23.x, s23.y };
#pragma unroll
                for (int a = 0; a < 4; a++)
#pragma unroll
                    for (int j = 0; j < 4; j++)
                        acc2[a][j] = fma2(ss[a], vp[j], acc2[a][j]);
            }
        }
        __syncthreads();   // all compute done before part (separate buffer) use

        // epilogue
        float inv[4];
#pragma unroll
        for (int j = 0; j < 4; j++) {
            float nlo, nhi;
            unpack2(accn2[j], nlo, nhi);
            inv[j] = TINV / fmaxf(sqrtf(nlo), 1e-12f);
        }

#pragma unroll
        for (int a = 0; a < 4; a++) {
            float dlo[4], dhi[4];
#pragma unroll
            for (int j = 0; j < 4; j++) unpack2(acc2[a][j], dlo[j], dhi[j]);
#pragma unroll
            for (int h = 0; h < 2; h++) {
                int s = si * 8 + 2 * a + h;
                const float* dv = h ? dhi : dlo;
                bool samevid = (g_s2b[s] == b);
                float sum = 0.f;
#pragma unroll
                for (int j = 0; j < 4; j++) {
                    int p = ptbase + pi * 4 + j;
                    if (p < P_) {
                        bool excl = false;
                        if (samevid) {
                            float io = iou2d[s * NN_ + g_midx[p]];
                            excl = (io > NEGIOU);
                        }
                        if (!excl) sum += __expf(dv[j] * inv[j]);
                    }
                }
                part[s * 16 + pi] = sum;
            }
        }
        __syncthreads();
        if (tid < S_) {
            float tot = 0.f;
#pragma unroll
            for (int kk = 0; kk < 16; kk++) tot += part[tid * 16 + kk];
            g_qpart[bid * S_ + tid] = tot;
        }
    } else {
        // ================= VIDEO ROLE =================
        int m = bid - QB;
        int sm = g_m2s[m];
        float* sv   = (float*)smem_raw;                  // [128]
        int*   sidx = (int*)(smem_raw + 512);            // [128]
        float* sv2  = (float*)(smem_raw + 1024);         // [256] normalized v
        float* alls = (float*)(smem_raw + 2048);         // [64]
        float* red  = (float*)(smem_raw + 2304);         // [4]

        // argmax over P of iou2ds[m, midx[p]] (tie -> lowest p)
        float best = -1e30f;
        int bi = 0;
        for (int p = tid; p < P_; p += 128) {
            float v = iou2ds[m * NN_ + g_midx[p]];
            if (v > best) { best = v; bi = p; }
        }
        sv[tid] = best; sidx[tid] = bi;
        __syncthreads();
        for (int o = 64; o; o >>= 1) {
            if (tid < o) {
                float vo = sv[tid + o]; int io = sidx[tid + o];
                if (vo > sv[tid] || (vo == sv[tid] && io < sidx[tid])) {
                    sv[tid] = vo; sidx[tid] = io;
                }
            }
            __syncthreads();
        }
        int pflat = g_midx[sidx[0]];
        __syncthreads();

        // load 2 channels per thread, compute norm
        float vc0 = video[((size_t)sm * C_ + tid) * NN_ + pflat];
        float vc1 = video[((size_t)sm * C_ + tid + 128) * NN_ + pflat];
        float x = vc0 * vc0 + vc1 * vc1;
#pragma unroll
        for (int o = 16; o; o >>= 1) x += __shfl_down_sync(0xffffffffu, x, o);
        if ((tid & 31) == 0) red[tid >> 5] = x;
        __syncthreads();
        float nrm = fmaxf(sqrtf(red[0] + red[1] + red[2] + red[3]), 1e-12f);
        sv2[tid] = vc0 / nrm;
        sv2[tid + 128] = vc1 / nrm;
        __syncthreads();

        // dots against all 64 normalized sentence vectors
        int w = tid >> 5, l = tid & 31;
#pragma unroll
        for (int k = 0; k < 16; k++) {
            int s = w * 16 + k;
            float acc = 0.f;
#pragma unroll
            for (int c = l; c < C_; c += 32) acc += sv2[c] * g_sfn[s * C_ + c];
#pragma unroll
            for (int o = 16; o; o >>= 1) acc += __shfl_down_sync(0xffffffffu, acc, o);
            if (l == 0) alls[s] = acc;
        }
        __syncthreads();
        if (tid == 0) {
            float pl = alls[sm] * TINV;
            float neg = 0.f;
            for (int s = 0; s < S_; s++)
                if (s != sm) neg += expf(alls[s] * TINV);
            g_pl[m] = pl;
            g_lossv[m] = logf(expf(pl) + neg) - pl;
        }
    }
}

// ---------------------------------------------------------------------------
// Kernel 3: qpart reduce (coalesced) + per-moment losses -> mean (1 x 1024)
// ---------------------------------------------------------------------------
__global__ void final_kernel(float* __restrict__ out) {
    int t = threadIdx.x;
    __shared__ float qn[16][S_];
    __shared__ float qq[S_];
    __shared__ float red[32];
    {
        int s  = t & 63;
        int i0 = t >> 6;            // 0..15
        float acc = 0.f;
        for (int i = i0; i < QB; i += 16)   // 33 coalesced, independent loads
            acc += g_qpart[i * S_ + s];
        qn[i0][s] = acc;
    }
    __syncthreads();
    if (t < S_) {
        float x = 0.f;
#pragma unroll
        for (int k = 0; k < 16; k++) x += qn[k][t];
        qq[t] = x;
    }
    __syncthreads();

    float v = 0.f;
    if (t < M_) {
        int sm = g_m2s[t];
        float pl = g_pl[t];
        float lq = logf(expf(pl) + qq[sm]) - pl;
        v = g_lossv[t] + lq;
    }
#pragma unroll
    for (int o = 16; o; o >>= 1) v += __shfl_down_sync(0xffffffffu, v, o);
    if ((t & 31) == 0) red[t >> 5] = v;
    __syncthreads();
    if (t == 0) {
        float acc = 0.f;
#pragma unroll
        for (int i = 0; i < 4; i++) acc += red[i];
        out[0] = acc / (float)M_;
    }
}

// ---------------------------------------------------------------------------
extern "C" void kernel_launch(void* const* d_in, const int* in_sizes, int n_in,
                              void* d_out, int out_size) {
    const float* video = (const float*)d_in[0];         // (S,C,N,N)
    const float* sents = (const float*)d_in[1];         // (S,C)
    const float* iou2d = (const float*)d_in[2];         // (S,N,N)
    const float* iou2ds = (const float*)d_in[3];        // (M,N,N)
    const int* nsent = (const int*)d_in[4];             // (B,)
    const int* ntarg = (const int*)d_in[5];             // (S,)
    float* out = (float*)d_out;

    sfnorm_setup_kernel<<<S_, 256>>>(sents, nsent, ntarg);
    mega_kernel<<<GRID, 128>>>(video, iou2d, iou2ds);
    final_kernel<<<1, 1024>>>(out);
}

// round 17
// speedup vs baseline: 1.3488x; 1.0390x over previous
#include <cuda_runtime.h>
#include <math.h>
#include <stdint.h>

#define S_ 64
#define C_ 256
#define NN_ 4096
#define B_ 16
#define M_ 128
#define P_ 2080
#define TINV 10.0f
#define NEGIOU 0.5f
#define TP 64
#define PTILES 33           // 33*64 = 2112 >= 2080
#define CK 16
#define CHUNKS (C_/CK)      // 16
#define QB (PTILES*B_)      // 528 query blocks
#define GRID (QB + M_)      // + 128 video blocks
#define NST 3               // cp.async pipeline depth

// scratch (device globals; no allocation allowed)
__device__ int   g_midx[P_];
__device__ int   g_b2s[B_];
__device__ int   g_m2s[M_];
__device__ int   g_s2b[S_];
__device__ float g_sfn[S_*C_];   // [s][c] row-major (video role)
__device__ float g_sft[C_*S_];   // [c][s] transposed (query role)
__device__ float g_pl[M_];
__device__ float g_lossv[M_];
__device__ float g_qpart[QB*S_];

// ---------------------------------------------------------------------------
// helpers
// ---------------------------------------------------------------------------
__device__ __forceinline__ void cpa4(void* dst, const void* src) {
    uint32_t d = (uint32_t)__cvta_generic_to_shared(dst);
    asm volatile("cp.async.ca.shared.global [%0], [%1], 4;" :: "r"(d), "l"(src));
}
__device__ __forceinline__ void cpa16(void* dst, const void* src) {
    uint32_t d = (uint32_t)__cvta_generic_to_shared(dst);
    asm volatile("cp.async.cg.shared.global [%0], [%1], 16;" :: "r"(d), "l"(src));
}
__device__ __forceinline__ void cpa_commit() { asm volatile("cp.async.commit_group;"); }
__device__ __forceinline__ void cpa_wait1()  { asm volatile("cp.async.wait_group 1;"); }
__device__ __forceinline__ void cpa_wait0()  { asm volatile("cp.async.wait_group 0;"); }

__device__ __forceinline__ uint64_t packdup(float x) {
    uint64_t r; asm("mov.b64 %0, {%1, %1};" : "=l"(r) : "f"(x)); return r;
}
__device__ __forceinline__ uint64_t fma2(uint64_t a, uint64_t b, uint64_t c) {
    uint64_t d; asm("fma.rn.f32x2 %0, %1, %2, %3;" : "=l"(d) : "l"(a), "l"(b), "l"(c));
    return d;
}
__device__ __forceinline__ void unpack2(uint64_t v, float& lo, float& hi) {
    asm("mov.b64 {%0, %1}, %2;" : "=f"(lo), "=f"(hi) : "l"(v));
}

// ---------------------------------------------------------------------------
// Kernel 1: sf normalize (64 blocks x 256) + transposed copy + setup (blk 0)
// mask2d is static config: triu(64x64), P=2080, generated analytically.
// ---------------------------------------------------------------------------
__global__ void sfnorm_setup_kernel(const float* __restrict__ sf,
                                    const int* __restrict__ nsent,
                                    const int* __restrict__ ntarg) {
    int s = blockIdx.x;
    int t = threadIdx.x; // == c

    __shared__ int sh_cs[B_ + 1];
    __shared__ int sh_ct[S_];
    __shared__ int sh_nt[S_];
    __shared__ int sh_ns[B_];
    __shared__ int sh_wtot;
    __shared__ float red[8];

    if (s == 0) {
        int lane = t & 31;
        int warp = t >> 5;
        if (warp == 0) {
            int v = (lane < B_) ? nsent[lane] : 0;
            if (lane < B_) sh_ns[lane] = v;
            int incl = v;
#pragma unroll
            for (int o = 1; o < 32; o <<= 1) {
                int up = __shfl_up_sync(0xffffffffu, incl, o);
                if (lane >= o) incl += up;
            }
            if (lane < B_) sh_cs[lane] = incl - v;
            if (lane == B_ - 1) sh_cs[B_] = incl;
        }
        if (warp == 1 || warp == 2) {
            int idx = (warp - 1) * 32 + lane;
            int v = ntarg[idx];
            sh_nt[idx] = v;
            int incl = v;
#pragma unroll
            for (int o = 1; o < 32; o <<= 1) {
                int up = __shfl_up_sync(0xffffffffu, incl, o);
                if (lane >= o) incl += up;
            }
            if (warp == 1) {
                sh_ct[idx] = incl - v;
                if (lane == 31) sh_wtot = incl;
            }
        }
        __syncthreads();
        if (warp == 2) {
            int idx = 32 + lane;
            int v = sh_nt[idx];
            int incl = v;
#pragma unroll
            for (int o = 1; o < 32; o <<= 1) {
                int up = __shfl_up_sync(0xffffffffu, incl, o);
                if (lane >= o) incl += up;
            }
            sh_ct[idx] = incl - v + sh_wtot;
        }
        if (t < 64) {
            int off = t * 64 - (t * (t - 1)) / 2;
            for (int c = t; c < 64; c++)
                g_midx[off + (c - t)] = t * 64 + c;
        }
        __syncthreads();
        if (t < B_) {
            int st = sh_cs[t];
            g_b2s[t] = st;
            for (int j = 0; j < sh_ns[t]; j++)
                if (st + j < S_) g_s2b[st + j] = t;
        }
        if (t < S_) {
            int st = sh_ct[t];
            for (int j = 0; j < sh_nt[t]; j++)
                if (st + j < M_) g_m2s[st + j] = t;
        }
    }

    float v = sf[s * C_ + t];
    float x = v * v;
#pragma unroll
    for (int o = 16; o; o >>= 1) x += __shfl_down_sync(0xffffffffu, x, o);
    if ((t & 31) == 0) red[t >> 5] = x;
    __syncthreads();
    if (t == 0) {
        float acc = 0.f;
#pragma unroll
        for (int i = 0; i < 8; i++) acc += red[i];
        red[0] = acc;
    }
    __syncthreads();
    float n = fmaxf(sqrtf(red[0]), 1e-12f);
    float nv = v / n;
    g_sfn[s * C_ + t] = nv;
    g_sft[t * S_ + s] = nv;
}

// ---------------------------------------------------------------------------
// Kernel 2 (mega): blocks [0,QB): inter-query; blocks [QB,QB+M): inter-video
// Query mainloop: R16 structure (CK=16, NST=3, single barrier/chunk), but
// norm FMA2s are REMOVED from the dot loop; instead every thread uniformly
// accumulates its loader-column's 8 channels (scalar LDS+FFMA) per chunk —
// norms computed once per column, no divergence, -20% FMA2 pipe load.
// ---------------------------------------------------------------------------
__global__ __launch_bounds__(128, 4) void mega_kernel(const float* __restrict__ video,
                                                      const float* __restrict__ iou2d,
                                                      const float* __restrict__ iou2ds) {
    __shared__ __align__(16) char smem_raw[NST*8192 + 4096];
    int bid = blockIdx.x;
    int tid = threadIdx.x;

    if (bid < QB) {
        // ================= QUERY ROLE =================
        float* vt   = (float*)smem_raw;                      // [NST][CK][TP] 12KB
        float* sfc  = (float*)(smem_raw + NST*4096);         // [NST][CK*64]  12KB
        float* part = (float*)(smem_raw + NST*8192);         // [64][16]       4KB

        int b  = bid / PTILES;
        int pt = bid - b * PTILES;
        int sb = g_b2s[b];
        int pi = tid & 15;     // p-group: p = ptbase + pi*4 + j
        int si = tid >> 4;     // s-group: s = si*8 + 2a + h

        int ptbase = pt * TP;
        int pcol_l = tid & 63; // loader's p column
        int ih = tid >> 6;     // loader's c-half
        int pc = ptbase + pcol_l;
        int fidx = g_midx[pc < P_ ? pc : (P_ - 1)];
        const float* vbase = video + (size_t)sb * C_ * NN_;

        uint64_t acc2[4][4];   // [a(s-pair)][j(p)]
        float vnorm = 0.f;     // this thread's column-half norm partial
#pragma unroll
        for (int a = 0; a < 4; a++)
#pragma unroll
            for (int j = 0; j < 4; j++) acc2[a][j] = 0ull;

        auto load_stage = [&](int chunk, int st) {
            int cb = chunk * CK;
            float* vdst = vt + st * CK * TP;
            float* sdst = sfc + st * CK * S_;
#pragma unroll
            for (int i2 = 0; i2 < 8; i2++) {
                int i = ih * 8 + i2;
                cpa4(&vdst[i * TP + pcol_l], vbase + (size_t)(cb + i) * NN_ + fidx);
            }
            const float* ssrc = g_sft + cb * S_;
#pragma unroll
            for (int k = 0; k < 2; k++) {
                int u = tid + k * 128;       // 16B unit index (256 units)
                cpa16(&sdst[u * 4], &ssrc[u * 4]);
            }
            cpa_commit();
        };

        load_stage(0, 0);
        load_stage(1, 1);

        for (int k = 0; k < CHUNKS; k++) {
            if (k < CHUNKS - 1) cpa_wait1(); else cpa_wait0();
            __syncthreads();   // chunk k visible; stage (k+2)%3 free
            if (k + 2 < CHUNKS) load_stage(k + 2, (k + 2) % NST);
            int st = k % NST;
            const float* vrow = vt + st * CK * TP;
            const float* srow = sfc + st * CK * S_;
#pragma unroll
            for (int i = 0; i < CK; i++) {
                float4 vld = *(const float4*)&vrow[i * TP + pi * 4];
                const ulonglong2* sp = (const ulonglong2*)&srow[i * S_ + si * 8];
                ulonglong2 s01 = sp[0];
                ulonglong2 s23 = sp[1];
                uint64_t vp[4];
                vp[0] = packdup(vld.x); vp[1] = packdup(vld.y);
                vp[2] = packdup(vld.z); vp[3] = packdup(vld.w);
                uint64_t ss[4] = { s01.x, s01.y, s23.x, s23.y };
#pragma unroll
                for (int a = 0; a < 4; a++)
#pragma unroll
                    for (int j = 0; j < 4; j++)
                        acc2[a][j] = fma2(ss[a], vp[j], acc2[a][j]);
            }
            // uniform norm pass: this thread's loader column, its 8 channels.
            // Stage k%3 stays valid until the NEXT iteration's barrier (the
            // prefetch that overwrites it is issued after that barrier).
#pragma unroll
            for (int i2 = 0; i2 < 8; i2++) {
                float vv = vrow[(ih * 8 + i2) * TP + pcol_l];
                vnorm = fmaf(vv, vv, vnorm);
            }
        }
        __syncthreads();   // mainloop done; part buffer free

        // combine per-column norm halves via part buffer
        part[pcol_l * 2 + ih] = vnorm;
        __syncthreads();
        float inv[4];
#pragma unroll
        for (int j = 0; j < 4; j++) {
            int col = pi * 4 + j;
            float tot = part[col * 2] + part[col * 2 + 1];
            inv[j] = TINV / fmaxf(sqrtf(tot), 1e-12f);
        }
        __syncthreads();   // before part reuse for exp sums

        // masked exp-sum epilogue
#pragma unroll
        for (int a = 0; a < 4; a++) {
            float dlo[4], dhi[4];
#pragma unroll
            for (int j = 0; j < 4; j++) unpack2(acc2[a][j], dlo[j], dhi[j]);
#pragma unroll
            for (int h = 0; h < 2; h++) {
                int s = si * 8 + 2 * a + h;
                const float* dv = h ? dhi : dlo;
                bool samevid = (g_s2b[s] == b);
                float sum = 0.f;
#pragma unroll
                for (int j = 0; j < 4; j++) {
                    int p = ptbase + pi * 4 + j;
                    if (p < P_) {
                        bool excl = false;
                        if (samevid) {
                            float io = iou2d[s * NN_ + g_midx[p]];
                            excl = (io > NEGIOU);
                        }
                        if (!excl) sum += __expf(dv[j] * inv[j]);
                    }
                }
                part[s * 16 + pi] = sum;
            }
        }
        __syncthreads();
        if (tid < S_) {
            float tot = 0.f;
#pragma unroll
            for (int kk = 0; kk < 16; kk++) tot += part[tid * 16 + kk];
            g_qpart[bid * S_ + tid] = tot;
        }
    } else {
        // ================= VIDEO ROLE =================
        int m = bid - QB;
        int sm = g_m2s[m];
        float* sv   = (float*)smem_raw;                  // [128]
        int*   sidx = (int*)(smem_raw + 512);            // [128]
        float* sv2  = (float*)(smem_raw + 1024);         // [256] normalized v
        float* alls = (float*)(smem_raw + 2048);         // [64]
        float* red  = (float*)(smem_raw + 2304);         // [4]

        // argmax over P of iou2ds[m, midx[p]] (tie -> lowest p)
        float best = -1e30f;
        int bi = 0;
        for (int p = tid; p < P_; p += 128) {
            float v = iou2ds[m * NN_ + g_midx[p]];
            if (v > best) { best = v; bi = p; }
        }
        sv[tid] = best; sidx[tid] = bi;
        __syncthreads();
        for (int o = 64; o; o >>= 1) {
            if (tid < o) {
                float vo = sv[tid + o]; int io = sidx[tid + o];
                if (vo > sv[tid] || (vo == sv[tid] && io < sidx[tid])) {
                    sv[tid] = vo; sidx[tid] = io;
                }
            }
            __syncthreads();
        }
        int pflat = g_midx[sidx[0]];
        __syncthreads();

        // load 2 channels per thread, compute norm
        float vc0 = video[((size_t)sm * C_ + tid) * NN_ + pflat];
        float vc1 = video[((size_t)sm * C_ + tid + 128) * NN_ + pflat];
        float x = vc0 * vc0 + vc1 * vc1;
#pragma unroll
        for (int o = 16; o; o >>= 1) x += __shfl_down_sync(0xffffffffu, x, o);
        if ((tid & 31) == 0) red[tid >> 5] = x;
        __syncthreads();
        float nrm = fmaxf(sqrtf(red[0] + red[1] + red[2] + red[3]), 1e-12f);
        sv2[tid] = vc0 / nrm;
        sv2[tid + 128] = vc1 / nrm;
        __syncthreads();

        // dots against all 64 normalized sentence vectors
        int w = tid >> 5, l = tid & 31;
#pragma unroll
        for (int k = 0; k < 16; k++) {
            int s = w * 16 + k;
            float acc = 0.f;
#pragma unroll
            for (int c = l; c < C_; c += 32) acc += sv2[c] * g_sfn[s * C_ + c];
#pragma unroll
            for (int o = 16; o; o >>= 1) acc += __shfl_down_sync(0xffffffffu, acc, o);
            if (l == 0) alls[s] = acc;
        }
        __syncthreads();
        if (tid == 0) {
            float pl = alls[sm] * TINV;
            float neg = 0.f;
            for (int s = 0; s < S_; s++)
                if (s != sm) neg += expf(alls[s] * TINV);
            g_pl[m] = pl;
            g_lossv[m] = logf(expf(pl) + neg) - pl;
        }
    }
}

// ---------------------------------------------------------------------------
// Kernel 3: qpart reduce (coalesced) + per-moment losses -> mean (1 x 1024)
// ---------------------------------------------------------------------------
__global__ void final_kernel(float* __restrict__ out) {
    int t = threadIdx.x;
    __shared__ float qn[16][S_];
    __shared__ float qq[S_];
    __shared__ float red[32];
    {
        int s  = t & 63;
        int i0 = t >> 6;            // 0..15
        float acc = 0.f;
        for (int i = i0; i < QB; i += 16)   // 33 coalesced, independent loads
            acc += g_qpart[i * S_ + s];
        qn[i0][s] = acc;
    }
    __syncthreads();
    if (t < S_) {
        float x = 0.f;
#pragma unroll
        for (int k = 0; k < 16; k++) x += qn[k][t];
        qq[t] = x;
    }
    __syncthreads();

    float v = 0.f;
    if (t < M_) {
        int sm = g_m2s[t];
        float pl = g_pl[t];
        float lq = logf(expf(pl) + qq[sm]) - pl;
        v = g_lossv[t] + lq;
    }
#pragma unroll
    for (int o = 16; o; o >>= 1) v += __shfl_down_sync(0xffffffffu, v, o);
    if ((t & 31) == 0) red[t >> 5] = v;
    __syncthreads();
    if (t == 0) {
        float acc = 0.f;
#pragma unroll
        for (int i = 0; i < 4; i++) acc += red[i];
        out[0] = acc / (float)M_;
    }
}

// ---------------------------------------------------------------------------
extern "C" void kernel_launch(void* const* d_in, const int* in_sizes, int n_in,
                              void* d_out, int out_size) {
    const float* video = (const float*)d_in[0];         // (S,C,N,N)
    const float* sents = (const float*)d_in[1];         // (S,C)
    const float* iou2d = (const float*)d_in[2];         // (S,N,N)
    const float* iou2ds = (const float*)d_in[3];        // (M,N,N)
    const int* nsent = (const int*)d_in[4];             // (B,)
    const int* ntarg = (const int*)d_in[5];             // (S,)
    float* out = (float*)d_out;

    sfnorm_setup_kernel<<<S_, 256>>>(sents, nsent, ntarg);
    mega_kernel<<<GRID, 128>>>(video, iou2d, iou2ds);
    final_kernel<<<1, 1024>>>(out);
}